// round 16
// baseline (speedup 1.0000x reference)
#include <cuda_runtime.h>
#include <cstdint>

// Problem constants
#define SDIM   64
#define CIN    16
#define COUTC  16
#define BATCH  4
#define NT     256

// Slab: 1188 rows ((3z * 6y) * 66 px), each row = 16 cin tf32 + 4 pad words.
// Row stride 20 words -> lane bank = (20*(lid>>2) + lid%4) mod 32, all distinct.
#define SROW_W      20
#define SLAB_ROWS   1188
#define SLAB_WORDS  (SLAB_ROWS * SROW_W)          // 23760
#define SMEM_TOTAL  (SLAB_WORDS * 4)              // 95040 bytes -> 2 CTAs/SM

// Per-lane-contiguous B image: [tap][nh][lane][4 words] = 27*2*32*4
#define B2_WORDS (27 * 2 * 32 * 4)

__device__ __align__(16) uint32_t g_B2[B2_WORDS];

#define CVT_TF32(d, f) asm("cvt.rna.tf32.f32 %0, %1;" : "=r"(d) : "f"(f))

// m16n8k8 tf32 MMA (sm_80+, compiles for plain sm_103 target)
#define MMA_TF32(d, a0, a1, a2, a3, b0, b1)                                   \
    asm volatile("mma.sync.aligned.m16n8k8.row.col.f32.tf32.tf32.f32 "        \
                 "{%0,%1,%2,%3}, {%4,%5,%6,%7}, {%8,%9}, {%0,%1,%2,%3};"      \
                 : "+f"((d)[0]), "+f"((d)[1]), "+f"((d)[2]), "+f"((d)[3])     \
                 : "r"(a0), "r"(a1), "r"(a2), "r"(a3), "r"(b0), "r"(b1))

// ---- Pre-kernel: tf32-convert weights into per-lane-contiguous B image ----
// Fragment mapping (validated in R14): lane (g,t), row n = nh*8+g, cin = t+4k.
__global__ void prebuild_b_kernel(const float* __restrict__ Wg)
{
    int e = blockIdx.x * blockDim.x + threadIdx.x;
    if (e >= B2_WORDS) return;
    int tap = e >> 8;              // /256
    int r   = e & 255;
    int nh  = r >> 7;
    int lid = (r >> 2) & 31;
    int k   = r & 3;
    int g   = lid >> 2;
    int t   = lid & 3;
    int n   = nh * 8 + g;
    int cin = t + 4 * k;
    float v = Wg[((size_t)n * CIN + cin) * 27 + tap];
    uint32_t h; CVT_TF32(h, v);
    g_B2[e] = h;
}

// ---- Main kernel: warp-level TF32 MMA implicit conv ----
__global__ void __launch_bounds__(NT, 2)
conv3d_mma_kernel(const float* __restrict__ X,
                  const float* __restrict__ Bias,
                  float* __restrict__ Out)
{
    extern __shared__ __align__(16) uint32_t smw[];
    const int tid = threadIdx.x;
    const int wid = tid >> 5;
    const int lid = tid & 31;
    const int g   = lid >> 2;     // groupID  (fragment row base)
    const int t   = lid & 3;      // threadID_in_group (fragment col base)

    const int z  = blockIdx.x;
    const int y0 = blockIdx.y * 4;
    const int b  = blockIdx.z;

    // ---- Slab fill: conflict-free STS.32 pattern (lanes = 8 rows x 4 cols) ----
    const float* Xb = X + (size_t)b * CIN * (SDIM * SDIM * SDIM);
#pragma unroll 1
    for (int step = 0; step < 19; ++step) {
        int row = step * 64 + wid * 8 + g;
        if (row < SLAB_ROWS) {
            int zy = row / 66, px = row - zy * 66;
            int zp = zy / 6,  yp = zy - zp * 6;
            int gz = z + zp - 1, gy = y0 + yp - 1, gx = px - 1;
            bool valid = ((unsigned)gz < SDIM) && ((unsigned)gy < SDIM) &&
                         ((unsigned)gx < SDIM);
#pragma unroll
            for (int j = 0; j < 4; ++j) {
                int c = t + 4 * j;
                float v = 0.0f;
                if (valid)
                    v = __ldg(Xb + ((size_t)c * SDIM * SDIM * SDIM) +
                              ((size_t)gz * SDIM + gy) * SDIM + gx);
                uint32_t h; CVT_TF32(h, v);
                smw[row * SROW_W + c] = h;
            }
        }
    }
    __syncthreads();

    // ---- Compute: warp = 16 x (x0) x 16 cout x 2 y (ypair) ----
    const int xg    = wid & 3;
    const int ypair = wid >> 2;
    const int x0    = xg * 16;

    float d[2][2][4];   // [yy][n-half][frag]
#pragma unroll
    for (int yy = 0; yy < 2; ++yy)
#pragma unroll
        for (int nh = 0; nh < 2; ++nh)
#pragma unroll
            for (int r = 0; r < 4; ++r) d[yy][nh][r] = 0.0f;

    const uint4* Bimg = reinterpret_cast<const uint4*>(g_B2);

#pragma unroll 1
    for (int kd = 0; kd < 3; ++kd) {
#pragma unroll
        for (int kh = 0; kh < 3; ++kh) {
#pragma unroll
            for (int kw = 0; kw < 3; ++kw) {
                const int tap = (kd * 3 + kh) * 3 + kw;

                // B fragments: 2 coalesced LDG.128 per lane (L1-resident image)
                uint4 b0 = __ldg(Bimg + (tap * 2 + 0) * 32 + lid);
                uint4 b1 = __ldg(Bimg + (tap * 2 + 1) * 32 + lid);

#pragma unroll
                for (int yy = 0; yy < 2; ++yy) {
                    const int yo = ypair * 2 + yy;
                    const int s  = (kd * 6 + yo + kh) * 66 + kw + x0;
                    const uint32_t* ap = smw + (s + g) * SROW_W + t;
                    uint32_t a0 = ap[0],   a1 = ap[4];        // row g  : cin t, t+4
                    uint32_t a2 = ap[8],   a3 = ap[12];       // row g  : cin t+8, t+12
                    uint32_t a4 = ap[160], a5 = ap[164];      // row g+8: cin t, t+4
                    uint32_t a6 = ap[168], a7 = ap[172];      // row g+8: cin t+8, t+12

                    // chunk0: cins 0-7 ; chunk1: cins 8-15
                    MMA_TF32(d[yy][0], a0, a4, a1, a5, b0.x, b0.y);
                    MMA_TF32(d[yy][1], a0, a4, a1, a5, b1.x, b1.y);
                    MMA_TF32(d[yy][0], a2, a6, a3, a7, b0.z, b0.w);
                    MMA_TF32(d[yy][1], a2, a6, a3, a7, b1.z, b1.w);
                }
            }
        }
    }

    // ---- Epilogue: D frag -> global, + bias ----
    const size_t COSTRIDE = (size_t)SDIM * SDIM * SDIM;
#pragma unroll
    for (int yy = 0; yy < 2; ++yy) {
        const int y = y0 + ypair * 2 + yy;
#pragma unroll
        for (int nh = 0; nh < 2; ++nh) {
            const int c0 = nh * 8 + 2 * t;
            const float bv0 = __ldg(Bias + c0);
            const float bv1 = __ldg(Bias + c0 + 1);
            float* o0 = Out + (((size_t)(b * COUTC + c0) * SDIM + z) * SDIM + y) * SDIM + x0;
            float* o1 = o0 + COSTRIDE;
            o0[g]     = d[yy][nh][0] + bv0;   // (row g,   col 2t)
            o1[g]     = d[yy][nh][1] + bv1;   // (row g,   col 2t+1)
            o0[g + 8] = d[yy][nh][2] + bv0;   // (row g+8, col 2t)
            o1[g + 8] = d[yy][nh][3] + bv1;   // (row g+8, col 2t+1)
        }
    }
}

extern "C" void kernel_launch(void* const* d_in, const int* in_sizes, int n_in,
                              void* d_out, int out_size)
{
    const float* x    = (const float*)d_in[0];
    const float* w    = (const float*)d_in[1];
    const float* bias = (const float*)d_in[2];
    float* out        = (float*)d_out;

    cudaFuncSetAttribute(conv3d_mma_kernel,
                         cudaFuncAttributeMaxDynamicSharedMemorySize, SMEM_TOTAL);

    prebuild_b_kernel<<<(B2_WORDS + NT - 1) / NT, NT>>>(w);

    dim3 grid(SDIM, SDIM / 4, BATCH);
    conv3d_mma_kernel<<<grid, NT, SMEM_TOTAL>>>(x, bias, out);
}

// round 17
// speedup vs baseline: 1.2936x; 1.2936x over previous
#include <cuda_runtime.h>
#include <cstdint>

// Problem constants
#define SDIM   64
#define CIN    16
#define COUTC  16
#define BATCH  4
#define NT     256

// Slab: 1188 rows ((3z * 6y) * 66 px), row = 16 words (64B), cin-PERMUTED:
// word (4t+i) holds cin (4i+t)  ->  lane (g,t) reads its A-frag as one LDS.128.
#define SROW_W      16
#define SLAB_ROWS   1188
#define SLAB_WORDS  (SLAB_ROWS * SROW_W)          // 19008
#define SMEM_TOTAL  (SLAB_WORDS * 4)              // 76032 bytes -> 3 CTAs/SM

// Per-lane-contiguous B image: [tap][nh][lane][4 words]
#define B2_WORDS (27 * 2 * 32 * 4)

__device__ __align__(16) uint32_t g_B2[B2_WORDS];

#define CVT_TF32(d, f) asm("cvt.rna.tf32.f32 %0, %1;" : "=r"(d) : "f"(f))

// m16n8k8 tf32 MMA (sm_80+, plain sm_103 target)
#define MMA_TF32(d, a0, a1, a2, a3, b0, b1)                                   \
    asm volatile("mma.sync.aligned.m16n8k8.row.col.f32.tf32.tf32.f32 "        \
                 "{%0,%1,%2,%3}, {%4,%5,%6,%7}, {%8,%9}, {%0,%1,%2,%3};"      \
                 : "+f"((d)[0]), "+f"((d)[1]), "+f"((d)[2]), "+f"((d)[3])     \
                 : "r"(a0), "r"(a1), "r"(a2), "r"(a3), "r"(b0), "r"(b1))

// ---- Pre-kernel: tf32-convert weights into per-lane B image ----
// lane (g,t), row n = nh*8+g, word k -> cin = t+4k
__global__ void prebuild_b_kernel(const float* __restrict__ Wg)
{
    int e = blockIdx.x * blockDim.x + threadIdx.x;
    if (e >= B2_WORDS) return;
    int tap = e >> 8;
    int r   = e & 255;
    int nh  = r >> 7;
    int lid = (r >> 2) & 31;
    int k   = r & 3;
    int g   = lid >> 2;
    int t   = lid & 3;
    int n   = nh * 8 + g;
    int cin = t + 4 * k;
    float v = Wg[((size_t)n * CIN + cin) * 27 + tap];
    uint32_t h; CVT_TF32(h, v);
    g_B2[e] = h;
}

// ---- Main kernel: warp-level TF32 MMA implicit conv ----
__global__ void __launch_bounds__(NT, 3)
conv3d_mma_kernel(const float* __restrict__ X,
                  const float* __restrict__ Bias,
                  float* __restrict__ Out)
{
    extern __shared__ __align__(16) uint32_t smw[];
    const int tid = threadIdx.x;
    const int wid = tid >> 5;
    const int lid = tid & 31;
    const int g   = lid >> 2;     // fragment row base
    const int t   = lid & 3;      // fragment col base

    const int z  = blockIdx.x;
    const int y0 = blockIdx.y * 4;
    const int b  = blockIdx.z;

    // ---- Slab fill: per-lane gather of cins {t,t+4,t+8,t+12} -> one STS.128 ----
    const float* Xb = X + (size_t)b * CIN * (SDIM * SDIM * SDIM);
#pragma unroll 1
    for (int step = 0; step < 19; ++step) {
        int row = step * 64 + wid * 8 + g;
        if (row < SLAB_ROWS) {
            int zy = row / 66, px = row - zy * 66;
            int zp = zy / 6,  yp = zy - zp * 6;
            int gz = z + zp - 1, gy = y0 + yp - 1, gx = px - 1;
            bool valid = ((unsigned)gz < SDIM) && ((unsigned)gy < SDIM) &&
                         ((unsigned)gx < SDIM);
            uint32_t h[4];
#pragma unroll
            for (int i = 0; i < 4; ++i) {
                int c = 4 * i + t;          // word i of this lane's group = cin 4i+t
                float v = 0.0f;
                if (valid)
                    v = __ldg(Xb + ((size_t)c * SDIM * SDIM * SDIM) +
                              ((size_t)gz * SDIM + gy) * SDIM + gx);
                CVT_TF32(h[i], v);
            }
            *reinterpret_cast<uint4*>(smw + row * SROW_W + 4 * t) =
                make_uint4(h[0], h[1], h[2], h[3]);
        }
    }
    __syncthreads();

    // ---- Compute: warp = 16 x (x0) x 16 cout x 2 y (ypair) ----
    const int xg    = wid & 3;
    const int ypair = wid >> 2;
    const int x0    = xg * 16;

    float d[2][2][4];   // [yy][n-half][frag]
#pragma unroll
    for (int yy = 0; yy < 2; ++yy)
#pragma unroll
        for (int nh = 0; nh < 2; ++nh)
#pragma unroll
            for (int r = 0; r < 4; ++r) d[yy][nh][r] = 0.0f;

    const uint4* Bimg = reinterpret_cast<const uint4*>(g_B2);
    const uint4* Aw   = reinterpret_cast<const uint4*>(smw) + t;   // +4t words

#pragma unroll 1
    for (int kd = 0; kd < 3; ++kd) {
#pragma unroll
        for (int kh = 0; kh < 3; ++kh) {
#pragma unroll
            for (int kw = 0; kw < 3; ++kw) {
                const int tap = (kd * 3 + kh) * 3 + kw;

                // B: 2 coalesced LDG.128 (L1-resident image)
                uint4 b0 = __ldg(Bimg + (tap * 2 + 0) * 32 + lid);
                uint4 b1 = __ldg(Bimg + (tap * 2 + 1) * 32 + lid);

#pragma unroll
                for (int yy = 0; yy < 2; ++yy) {
                    const int yo = ypair * 2 + yy;
                    const int s  = (kd * 6 + yo + kh) * 66 + kw + x0;
                    // A frag: one LDS.128 per row-half (cins t,t+4,t+8,t+12)
                    uint4 q0 = Aw[(s + g) * 4];         // row g     (x4 uint4/row)
                    uint4 q1 = Aw[(s + g + 8) * 4];     // row g+8

                    MMA_TF32(d[yy][0], q0.x, q1.x, q0.y, q1.y, b0.x, b0.y);
                    MMA_TF32(d[yy][1], q0.x, q1.x, q0.y, q1.y, b1.x, b1.y);
                    MMA_TF32(d[yy][0], q0.z, q1.z, q0.w, q1.w, b0.z, b0.w);
                    MMA_TF32(d[yy][1], q0.z, q1.z, q0.w, q1.w, b1.z, b1.w);
                }
            }
        }
    }

    // ---- Epilogue: D frag -> global, + bias ----
    const size_t COSTRIDE = (size_t)SDIM * SDIM * SDIM;
#pragma unroll
    for (int yy = 0; yy < 2; ++yy) {
        const int y = y0 + ypair * 2 + yy;
#pragma unroll
        for (int nh = 0; nh < 2; ++nh) {
            const int c0 = nh * 8 + 2 * t;
            const float bv0 = __ldg(Bias + c0);
            const float bv1 = __ldg(Bias + c0 + 1);
            float* o0 = Out + (((size_t)(b * COUTC + c0) * SDIM + z) * SDIM + y) * SDIM + x0;
            float* o1 = o0 + COSTRIDE;
            o0[g]     = d[yy][nh][0] + bv0;
            o1[g]     = d[yy][nh][1] + bv1;
            o0[g + 8] = d[yy][nh][2] + bv0;
            o1[g + 8] = d[yy][nh][3] + bv1;
        }
    }
}

extern "C" void kernel_launch(void* const* d_in, const int* in_sizes, int n_in,
                              void* d_out, int out_size)
{
    const float* x    = (const float*)d_in[0];
    const float* w    = (const float*)d_in[1];
    const float* bias = (const float*)d_in[2];
    float* out        = (float*)d_out;

    cudaFuncSetAttribute(conv3d_mma_kernel,
                         cudaFuncAttributeMaxDynamicSharedMemorySize, SMEM_TOTAL);

    prebuild_b_kernel<<<(B2_WORDS + NT - 1) / NT, NT>>>(w);

    dim3 grid(SDIM, SDIM / 4, BATCH);
    conv3d_mma_kernel<<<grid, NT, SMEM_TOTAL>>>(x, bias, out);
}